// round 17
// baseline (speedup 1.0000x reference)
#include <cuda_runtime.h>
#include <math.h>

#define MM 48
#define LL 48
#define NN 256
#define NT 128            // threads per CTA (= per sample)
#define KPJ 12            // k's per thread (4-aligned contiguous segment)
#define STR2 64           // float2 row stride for ab (16B-aligned)
#define SLOTS (NT * KPJ)  // 1536 checkpoint slots
#define CPB 8             // checkpoint rows: cp[b] = SUF(6b+5)

// smem floats: ab float2[48*64] (=6144 f) | cp[8*1536] | u[48] | prt[72]
#define SM_AB  0
#define SM_CP  (2 * LL * STR2)
#define SM_U   (SM_CP + CPB * SLOTS)
#define SM_PRT (SM_U + LL)
#define SMEMF  (SM_PRT + 72)

typedef unsigned long long u64;

// Accurate f32 sincos: Cody-Waite FMA range reduction + Taylor polys.
// |x| < ~80, ~1-2 ulp, immune to --use_fast_math (no libm).
__device__ __forceinline__ void sincos_acc(float x, float* s, float* c) {
    float kf = rintf(x * 0.63661977236758134f);
    int k = (int)kf;
    float r = fmaf(kf, -1.57079637050628662109375f, x);
    r = fmaf(kf, 4.37113882867379290e-8f, r);
    float r2 = r * r;
    float ps = fmaf(r2, 2.7557314297e-06f, -1.9841270114e-04f);
    ps = fmaf(r2, ps, 8.3333337680e-03f);
    ps = fmaf(r2, ps, -1.6666667163e-01f);
    float sr = fmaf(r * r2, ps, r);
    float pc = fmaf(r2, -2.7557314297e-07f, 2.4760126951e-05f);
    pc = fmaf(r2, pc, -1.3888889225e-03f);
    pc = fmaf(r2, pc, 4.1666667908e-02f);
    float cr = fmaf(r2 * r2, pc, fmaf(r2, -0.5f, 1.0f));
    switch (k & 3) {
        case 0: *s = sr;  *c = cr;  break;
        case 1: *s = cr;  *c = -sr; break;
        case 2: *s = -sr; *c = -cr; break;
        default:*s = -cr; *c = sr;  break;
    }
}

// 12 float2 <-> regs (6x LDS.128); 12 floats <-> regs (3x LDS/STS.128)
__device__ __forceinline__ void ld12f2(const float2* p, float2* v) {
    const float4* q = reinterpret_cast<const float4*>(p);
#pragma unroll
    for (int i = 0; i < 6; i++) {
        float4 t = q[i];
        v[2 * i]     = make_float2(t.x, t.y);
        v[2 * i + 1] = make_float2(t.z, t.w);
    }
}
__device__ __forceinline__ void ld12(const float* p, float* v) {
    const float4* q = reinterpret_cast<const float4*>(p);
    float4 x = q[0], y = q[1], z = q[2];
    v[0] = x.x; v[1] = x.y; v[2]  = x.z; v[3]  = x.w;
    v[4] = y.x; v[5] = y.y; v[6]  = y.z; v[7]  = y.w;
    v[8] = z.x; v[9] = z.y; v[10] = z.z; v[11] = z.w;
}
__device__ __forceinline__ void st12(float* p, const float* v) {
    float4* q = reinterpret_cast<float4*>(p);
    q[0] = make_float4(v[0], v[1], v[2],  v[3]);
    q[1] = make_float4(v[4], v[5], v[6],  v[7]);
    q[2] = make_float4(v[8], v[9], v[10], v[11]);
}

__global__ __launch_bounds__(NT, 2) void fused_kernel(
    const float* __restrict__ inp,      // (N,L)
    const float* __restrict__ theta,    // (L,M)
    const float* __restrict__ coef,     // (M,)
    const float* __restrict__ rand_u,   // (L,N)
    float* __restrict__ out)            // N*L bits then N probs
{
    extern __shared__ float sm[];
    float2* ab  = reinterpret_cast<float2*>(sm + SM_AB);  // [l*STR2 + k]
    float*  cp  = sm + SM_CP;
    float*  ush = sm + SM_U;
    float*  prt = sm + SM_PRT;

    const int n = blockIdx.x, tid = threadIdx.x;
    const int lane = tid & 31, wid = tid >> 5;

    // ---- Phase A: AoS embedding tile (f32 rounding matches reference) ----
    const float PI2F = 1.57079637050628662109375f;
#pragma unroll
    for (int e = tid; e < LL * STR2; e += NT) {
        int l = e / STR2, c = e - l * STR2;
        float a = 0.f, b = 0.f;
        if (c < MM) {
            float ang = inp[n * LL + l] * ((float)(c + 1) * PI2F);
            float sv, cv; sincos_acc(ang, &sv, &cv);
            float st, ct; sincos_acc(theta[l * MM + c], &st, &ct);
            float cf = coef[c];
            a = cf * (ct * cv - st * sv);
            b = cf * (st * cv + ct * sv);
        }
        ab[e] = make_float2(a, b);
    }
    if (tid < LL) ush[tid] = rand_u[tid * NN + n];
    __syncthreads();

    // ---- segment decode: thread owns m and k in [kst, kst+11], kst % 4 == 0 ----
    int m = 47, kst = 48;                 // default: idle thread (reads zero pad)
    {
        int t = tid;
        for (int mm = 0; mm < MM; mm++) {
            int s = mm & ~3;
            int nseg = (MM - s + KPJ - 1) / KPJ;
            if (t < nseg) { m = mm; kst = s + t * KPJ; break; }
            t -= nseg;
        }
    }

    // ---- Phase B: backward scan; checkpoint SUF (weight baked) at l%6==5 ----
    {
        float run[KPJ];
#pragma unroll
        for (int j = 0; j < KPJ; j++) {
            int k = kst + j;
            run[j] = (k < m || k >= MM) ? 0.f : ((k == m) ? 1.f : 2.f);
        }
        for (int l = LL - 1; l >= 0; l--) {
            if ((l % 6) == 5)
                st12(cp + (l / 6) * SLOTS + tid * KPJ, run);
            float2 mv = ab[l * STR2 + m];
            float2 kv[KPJ];
            ld12f2(ab + l * STR2 + kst, kv);
#pragma unroll
            for (int j = 0; j < KPJ; j++)
                run[j] *= fmaf(mv.x, kv[j].x, mv.y * kv[j].y);
        }
    }
    // cp rows written and read by the same thread — no barrier needed.

    float P[KPJ];
#pragma unroll
    for (int j = 0; j < KPJ; j++)
        P[j] = (kst + j < m || kst + j >= MM) ? 0.f : 1.f;

    // suffix registers: r5 = SUF(6b+5) = cp[b];
    // r2 = SUF(6b+2) = r5 * d(6b+5) * d(6b+4) * d(6b+3)
    float r2[KPJ], r5[KPJ];
    auto dotmul = [&](int l, float* dst) {
        float2 mv = ab[l * STR2 + m];
        float2 kv[KPJ];
        ld12f2(ab + l * STR2 + kst, kv);
#pragma unroll
        for (int j = 0; j < KPJ; j++)
            dst[j] *= fmaf(mv.x, kv[j].x, mv.y * kv[j].y);
    };
    auto rebuild = [&](int b) {
        ld12(cp + b * SLOTS + tid * KPJ, r5);
#pragma unroll
        for (int j = 0; j < KPJ; j++) r2[j] = r5[j];
        dotmul(6 * b + 5, r2);
        dotmul(6 * b + 4, r2);
        dotmul(6 * b + 3, r2);
    };
    rebuild(0);

    float denom0 = 1.f;
    int Kexp = 0;
    u64 bits = 0ull;

    // ---- Phase C: 16 three-site rounds (8 speculative sums, 1 barrier each) ----
    // T_{b1,b2,b3} = sum_j P*cc1_{b1}*cc2_{b2}*cc3_{b3}*SUF(l0+2).
    auto round3 = [&](int l0, const float* suf, int bnext, int par) {
        float uv1 = ush[l0], uv2 = ush[l0 + 1], uv3 = ush[l0 + 2];
        float2 m1 = ab[l0 * STR2 + m];
        float2 m2 = ab[(l0 + 1) * STR2 + m];
        float2 m3 = ab[(l0 + 2) * STR2 + m];
        float2 k1[KPJ], k2[KPJ], k3[KPJ];
        ld12f2(ab + l0 * STR2 + kst, k1);
        ld12f2(ab + (l0 + 1) * STR2 + kst, k2);
        ld12f2(ab + (l0 + 2) * STR2 + kst, k3);

        float pa[KPJ], pb[KPJ];    // P*cc1_{0}, P*cc1_{1} (live across barrier)
        float t[8];
#pragma unroll
        for (int s = 0; s < 8; s++) t[s] = 0.f;
#pragma unroll
        for (int j = 0; j < KPJ; j++) {
            float aa1 = m1.x * k1[j].x, bb1 = m1.y * k1[j].y;
            float aa2 = m2.x * k2[j].x, bb2 = m2.y * k2[j].y;
            float a3s = (m3.x * k3[j].x) * suf[j];
            float b3s = (m3.y * k3[j].y) * suf[j];
            pa[j] = P[j] * aa1; pb[j] = P[j] * bb1;
            float paa = pa[j] * aa2, pab = pa[j] * bb2;
            float pba = pb[j] * aa2, pbb = pb[j] * bb2;
            t[0] = fmaf(paa, a3s, t[0]); t[1] = fmaf(paa, b3s, t[1]);
            t[2] = fmaf(pab, a3s, t[2]); t[3] = fmaf(pab, b3s, t[3]);
            t[4] = fmaf(pba, a3s, t[4]); t[5] = fmaf(pba, b3s, t[5]);
            t[6] = fmaf(pbb, a3s, t[6]); t[7] = fmaf(pbb, b3s, t[7]);
        }
#pragma unroll
        for (int s = 0; s < 8; s++) {
#pragma unroll
            for (int o = 16; o; o >>= 1)
                t[s] += __shfl_xor_sync(0xffffffffu, t[s], o);
        }
        if (lane == 0) {
#pragma unroll
            for (int s = 0; s < 8; s++) prt[par + s * 4 + wid] = t[s];
        }
        if (bnext >= 0) rebuild(bnext);    // fills bar wait, bit-independent
        __syncthreads();

        // redundant decisions (identical on all threads)
        float T[8];
        {
            const float4* q = reinterpret_cast<const float4*>(prt + par);
#pragma unroll
            for (int s = 0; s < 8; s++) {
                float4 v = q[s];
                T[s] = (v.x + v.y) + (v.z + v.w);
            }
        }
        // site l0 (b1): S1 = T[4..7]
        float S1a = (T[4] + T[5]) + (T[6] + T[7]);
        float S0a = (T[0] + T[1]) + (T[2] + T[3]);
        float den1 = fabsf(S0a + S1a);
        int b1 = (uv1 * den1 < fabsf(S1a)) ? 1 : 0;
        if (l0 == 0) denom0 = den1;
        const int base = b1 << 2;
        // site l0+1 (b2)
        float S1b = T[base + 2] + T[base + 3];
        float den2 = fabsf((T[base + 0] + T[base + 1]) + S1b);
        int b2 = (uv2 * den2 < fabsf(S1b)) ? 1 : 0;
        // site l0+2 (b3)
        float S1c = T[base + (b2 << 1) + 1];
        float den3 = fabsf(T[base + (b2 << 1)] + S1c);
        int b3 = (uv3 * den3 < fabsf(S1c)) ? 1 : 0;

        int eb = (__float_as_int(den3) >> 23) & 0xFF;   // exact 2^-k renorm
        int kk = eb ? (eb - 127) >> 1 : 0;
        Kexp += kk;
        float scale = __int_as_float((127 - kk) << 23);
        bits |= ((u64)b1 << l0) | ((u64)b2 << (l0 + 1)) | ((u64)b3 << (l0 + 2));

        // P update: selected site-2/3 factors recomputed from smem (low regs)
        {
            float2 mv2 = ab[(l0 + 1) * STR2 + m];
            float2 mv3 = ab[(l0 + 2) * STR2 + m];
            float fac = (b2 ? mv2.y : mv2.x) * (b3 ? mv3.y : mv3.x) * scale;
            float2 kv2[KPJ], kv3[KPJ];
            ld12f2(ab + (l0 + 1) * STR2 + kst, kv2);
            ld12f2(ab + (l0 + 2) * STR2 + kst, kv3);
#pragma unroll
            for (int j = 0; j < KPJ; j++) {
                float s2 = b2 ? kv2[j].y : kv2[j].x;
                float s3 = b3 ? kv3[j].y : kv3[j].x;
                P[j] = (b1 ? pb[j] : pa[j]) * (s2 * s3) * fac;
            }
        }
    };

#pragma unroll 1
    for (int b = 0; b < CPB; b++) {
        round3(6 * b,     r2, -1, 0);
        round3(6 * b + 3, r5, (b + 1 < CPB) ? b + 1 : -1, 32);
    }

    // ---- epilogue: final inner = sum w*P (true value * 2^Kexp), outputs ----
    float sf = 0.f;
#pragma unroll
    for (int j = 0; j < KPJ; j++) {
        int k = kst + j;
        float w = (k < m || k >= MM) ? 0.f : ((k == m) ? 1.f : 2.f);
        sf += w * P[j];
    }
#pragma unroll
    for (int o = 16; o; o >>= 1) sf += __shfl_xor_sync(0xffffffffu, sf, o);
    if (lane == 0) prt[64 + wid] = sf;
    __syncthreads();

    if (tid < LL) out[n * LL + tid] = (float)((bits >> tid) & 1ull);
    if (tid == 0) {
        double Sf = (double)((prt[64] + prt[65]) + (prt[66] + prt[67]));
        double pmv = ldexp(fabs(Sf), Kexp) / (double)denom0;
        out[NN * LL + n] = (float)pmv;
    }
}

extern "C" void kernel_launch(void* const* d_in, const int* in_sizes, int n_in,
                              void* d_out, int out_size) {
    const float* inp    = (const float*)d_in[0];   // (N,L)
    const float* theta  = (const float*)d_in[1];   // (L,M)
    const float* coef   = (const float*)d_in[2];   // (M,)
    const float* rand_u = (const float*)d_in[3];   // (L,N)
    float* out = (float*)d_out;

    static int smem_set = 0;
    if (!smem_set) {
        cudaFuncSetAttribute(fused_kernel,
                             cudaFuncAttributeMaxDynamicSharedMemorySize,
                             SMEMF * (int)sizeof(float));
        smem_set = 1;
    }
    fused_kernel<<<NN, NT, SMEMF * sizeof(float)>>>(inp, theta, coef, rand_u, out);
}